// round 12
// baseline (speedup 1.0000x reference)
#include <cuda_runtime.h>
#include <cuda_fp16.h>
#include <cstdint>

#define HH 256
#define WW 256
#define ICH 16
#define HWSZ (HH * WW)

// votes scratch, fp16, NHWC: ((n*H+h)*W+w)*128 + oc   (oc = np*16+lp)
__device__ __half g_votes[(size_t)16 * HH * WW * 128];

// ---- conv smem layout ----
// Input strips: 260 w-slots (slot = w+2), 16 ic fp16 = 32B/slot, XOR swizzle:
// 16B unit u stored at u ^ ((slot>>2)&1). 6-row ring.
#define STRIPB 8320                   // 260 * 32
#define WF_OFF (6 * STRIPB)           // 49920
// W fragment cache: [25 tap][16 ntile][32 lane] * 8B = 102400
#define SMEM_TOTAL (WF_OFF + 102400)  // 152320  -> 1 CTA/SM

__device__ __forceinline__ void mma_f16(float* c, const uint32_t* a,
                                        const uint32_t* b) {
    asm volatile(
        "mma.sync.aligned.m16n8k16.row.col.f32.f16.f16.f32 "
        "{%0,%1,%2,%3}, {%4,%5,%6,%7}, {%8,%9}, {%0,%1,%2,%3};"
        : "+f"(c[0]), "+f"(c[1]), "+f"(c[2]), "+f"(c[3])
        : "r"(a[0]), "r"(a[1]), "r"(a[2]), "r"(a[3]), "r"(b[0]), "r"(b[1]));
}
__device__ __forceinline__ void ldm_x4(uint32_t* r, uint32_t addr) {
    asm volatile(
        "ldmatrix.sync.aligned.m8n8.x4.shared.b16 {%0,%1,%2,%3}, [%4];"
        : "=r"(r[0]), "=r"(r[1]), "=r"(r[2]), "=r"(r[3]) : "r"(addr));
}
__device__ __forceinline__ uint32_t smem_u32(const void* p) {
    uint32_t a;
    asm("{ .reg .u64 t; cvta.to.shared.u64 t, %1; cvt.u32.u64 %0, t; }"
        : "=r"(a) : "l"(p));
    return a;
}

// ---------------------------------------------------------------------------
// Conv: grid = 16 n * 16 h-chunks = 256 CTAs, 256 thr, 1 CTA/SM.
// CTA: 16 h-rows, M=256 px (full width), N=128 oc (full). Warp tile:
// mg = warp&3 (64 px, 4 m-tiles), ng = warp>>2 (64 oc, 8 n-tiles);
// acc = 128 regs. 128 B smem / MMA (crossbar-balanced). Single-pass fp16.
// Numerics identical to R10 (same tap order, same conversions).
// ---------------------------------------------------------------------------
__global__ __launch_bounds__(256, 1)
void conv_votes_mma(const float* __restrict__ x, const float* __restrict__ Wg) {
    extern __shared__ char smem[];
    const uint32_t sb = smem_u32(smem);
    const int tid  = threadIdx.x;
    const int warp = tid >> 5, lane = tid & 31;
    const int gid  = lane >> 2, tig = lane & 3;
    const int mg   = warp & 3, ng = warp >> 2;

    const int b  = blockIdx.x;
    const int n  = b & 15;
    const int h0 = (b >> 4) << 4;

    const float* xn = x + (size_t)n * ICH * HWSZ;

    // ---- W fragment cache: entry e = (tap*16+nt)*32 + lane, 8B ----
    for (int e = tid; e < 25 * 16 * 32; e += 256) {
        int l = e & 31, nt = (e >> 5) & 15, tap = e >> 9;
        int g = l >> 2, t = l & 3;
        const float* wr = Wg + (size_t)(nt * 8 + g) * 400 + tap;
        __half2* dst = (__half2*)(smem + WF_OFF + (size_t)e * 8);
        dst[0] = __halves2half2(__float2half(wr[(2 * t) * 25]),
                                __float2half(wr[(2 * t + 1) * 25]));
        dst[1] = __halves2half2(__float2half(wr[(2 * t + 8) * 25]),
                                __float2half(wr[(2 * t + 9) * 25]));
    }

    // ---- staging: 544 units; unit j: ic2 = j&7, qi = j>>3 (0..67) ----
    auto ldg_unit = [&](const float* xr, bool hok, int ic2, int qi, float4& r0,
                        float4& r1) {
        int q = qi - 1;
        r0 = make_float4(0.f, 0.f, 0.f, 0.f);
        r1 = r0;
        if (hok && (unsigned)q < 64u) {
            r0 = *(const float4*)(xr + (size_t)(2 * ic2) * HWSZ + q * 4);
            r1 = *(const float4*)(xr + (size_t)(2 * ic2 + 1) * HWSZ + q * 4);
        }
    };
    auto sts_unit = [&](const float4& r0, const float4& r1, int ic2, int qi,
                        char* bh) {
        const float a0[4] = {r0.x, r0.y, r0.z, r0.w};
        const float a1[4] = {r1.x, r1.y, r1.z, r1.w};
        const int ubit = ic2 >> 2, ylo = (ic2 & 3) << 2;
        const int sbase = ((qi - 1) << 2) + 2;
#pragma unroll
        for (int d = 0; d < 4; d++) {
            int dd = (d + qi) & 3;
            int slot = sbase + dd;
            if ((unsigned)slot < 260u) {
                int off = slot * 32 + (((ubit ^ (slot >> 2)) & 1) << 4) + ylo;
                *(__half2*)(bh + off) =
                    __float22half2_rn(make_float2(a0[dd], a1[dd]));
            }
        }
    };
    auto stage_row = [&](int h_in) {
        const bool hok = (unsigned)h_in < 256u;
        const float* xr = xn + (size_t)(hok ? h_in : 0) * WW;
        char* bh = smem + ((h_in + 600) % 6) * STRIPB;
        float4 r0, r1;
        ldg_unit(xr, hok, tid & 7, tid >> 3, r0, r1);
        sts_unit(r0, r1, tid & 7, tid >> 3, bh);
        int j = tid + 256;
        ldg_unit(xr, hok, j & 7, j >> 3, r0, r1);
        sts_unit(r0, r1, j & 7, j >> 3, bh);
        if (tid < 32) {
            j = tid + 512;
            ldg_unit(xr, hok, j & 7, j >> 3, r0, r1);
            sts_unit(r0, r1, j & 7, j >> 3, bh);
        }
    };

    // Prologue rows h0-2 .. h0+2
    stage_row(h0 - 2);
    stage_row(h0 - 1);
    stage_row(h0);
    stage_row(h0 + 1);
    stage_row(h0 + 2);
    __syncthreads();

    float acc[4][8][4];
#pragma unroll
    for (int m = 0; m < 4; m++)
#pragma unroll
        for (int nt = 0; nt < 8; nt++)
#pragma unroll
            for (int r = 0; r < 4; r++) acc[m][nt][r] = 0.f;

    // ldmatrix lane geometry: warp's px base = mg*64
    const int r8  = lane & 7;
    const int sA0 = (mg << 6) + r8 + (((lane >> 3) & 1) << 3);
    const int uK  = lane >> 4;

    for (int it = 0; it < 16; it++) {
        const int h = h0 + it;
        const int hs = h + 3;
        const bool hok = hs < 256;

        // Phase 1: prefetch next row (2 units/thread) into registers
        float4 p0[2], p1[2];
        {
            const float* xr = xn + (size_t)(hok ? hs : 0) * WW;
            ldg_unit(xr, hok, tid & 7, tid >> 3, p0[0], p1[0]);
            int j = tid + 256;
            ldg_unit(xr, hok, j & 7, j >> 3, p0[1], p1[1]);
        }

        // Phase 2: 25 taps x (4 m x 8 nt) single-pass MMAs
#pragma unroll 1
        for (int ky = 0; ky < 5; ky++) {
            const uint32_t rb32 = sb + ((h - 2 + ky + 600) % 6) * STRIPB;
#pragma unroll
            for (int kx = 0; kx < 5; kx++) {
                const int tap = ky * 5 + kx;
                uint32_t ah[4][4];
#pragma unroll
                for (int m = 0; m < 4; m++) {
                    int s = sA0 + (m << 4) + kx;
                    ldm_x4(ah[m], rb32 + s * 32
                                  + (((uK ^ (s >> 2)) & 1) << 4));
                }
                uint32_t bf[8][2];
#pragma unroll
                for (int nt = 0; nt < 8; nt++) {
                    uint2 vb = *(const uint2*)(smem + WF_OFF
                        + ((tap * 16 + (ng << 3) + nt) << 8) + lane * 8);
                    bf[nt][0] = vb.x;
                    bf[nt][1] = vb.y;
                }
#pragma unroll
                for (int m = 0; m < 4; m++)
#pragma unroll
                    for (int nt = 0; nt < 8; nt++)
                        mma_f16(acc[m][nt], ah[m], bf[nt]);
            }
        }

        // Phase 3: store prefetched row into ring slot (h+3)%6
        {
            char* bh = smem + (hs % 6) * STRIPB;
            sts_unit(p0[0], p1[0], tid & 7, tid >> 3, bh);
            int j = tid + 256;
            sts_unit(p0[1], p1[1], j & 7, j >> 3, bh);
            if (tid < 32) {
                j = tid + 512;
                float4 r0, r1;
                ldg_unit(xn + (size_t)(hok ? hs : 0) * WW, hok, j & 7, j >> 3,
                         r0, r1);
                sts_unit(r0, r1, j & 7, j >> 3, bh);
            }
        }

        // Phase 4: epilogue — D row to g_votes (fp16, NHWC, full 128 oc)
        {
            __half* vrow = &g_votes[(((size_t)n * HH + h) * WW) * 128];
#pragma unroll
            for (int m = 0; m < 4; m++) {
                int px = (mg << 6) + (m << 4) + gid;
#pragma unroll
                for (int nt = 0; nt < 8; nt++) {
                    int oc = (ng << 6) + (nt << 3) + (tig << 1);
                    *(__half2*)&vrow[(size_t)px * 128 + oc] =
                        __float22half2_rn(make_float2(acc[m][nt][0],
                                                      acc[m][nt][1]));
                    *(__half2*)&vrow[(size_t)(px + 8) * 128 + oc] =
                        __float22half2_rn(make_float2(acc[m][nt][2],
                                                      acc[m][nt][3]));
                    acc[m][nt][0] = 0.f; acc[m][nt][1] = 0.f;
                    acc[m][nt][2] = 0.f; acc[m][nt][3] = 0.f;
                }
            }
        }
        __syncthreads();
    }
}

// ---------------------------------------------------------------------------
// Routing: unchanged from R10 (bit-identical numerics).
// ---------------------------------------------------------------------------
__global__ __launch_bounds__(256)
void routing_kernel(float* __restrict__ out) {
    __shared__ float out_s[8][132];

    const int tid = threadIdx.x;
    const int warp = tid >> 5, lane = tid & 31;
    const int np = lane & 7, lpg = lane >> 3;
    const int pixBase = blockIdx.x << 3;
    const int pix = pixBase + warp;
    const int b = pix >> 16;
    const int hw = pix & 65535;

    float v[4][4];
#pragma unroll
    for (int nc = 0; nc < 4; nc++) {
        const __half2* vp = (const __half2*)
            &g_votes[(((size_t)(b * 4 + nc) << 16) + hw) * 128 + np * 16 + lpg * 4];
        float2 a = __half22float2(vp[0]);
        float2 c2 = __half22float2(vp[1]);
        v[nc][0] = a.x; v[nc][1] = a.y; v[nc][2] = c2.x; v[nc][3] = c2.y;
    }

    float sims[4] = {0.f, 0.f, 0.f, 0.f};
    float parent[4];

#pragma unroll
    for (int it = 0; it < 3; it++) {
        float c[4];
        if (it == 0) {
            c[0] = c[1] = c[2] = c[3] = 0.125f;
        } else {
#pragma unroll
            for (int nc = 0; nc < 4; nc++) {
                float e = __expf(sims[nc]);
                float s = e;
                s += __shfl_xor_sync(0xffffffffu, s, 1);
                s += __shfl_xor_sync(0xffffffffu, s, 2);
                s += __shfl_xor_sync(0xffffffffu, s, 4);
                c[nc] = e / s;
            }
        }
        float pu[4];
#pragma unroll
        for (int j = 0; j < 4; j++)
            pu[j] = c[0] * v[0][j] + c[1] * v[1][j] + c[2] * v[2][j]
                  + c[3] * v[3][j];
        float sq = pu[0] * pu[0] + pu[1] * pu[1] + pu[2] * pu[2] + pu[3] * pu[3];

        if (it < 2) {
            float dp[4];
#pragma unroll
            for (int nc = 0; nc < 4; nc++)
                dp[nc] = v[nc][0] * pu[0] + v[nc][1] * pu[1]
                       + v[nc][2] * pu[2] + v[nc][3] * pu[3];
            sq += __shfl_xor_sync(0xffffffffu, sq, 8);
#pragma unroll
            for (int nc = 0; nc < 4; nc++)
                dp[nc] += __shfl_xor_sync(0xffffffffu, dp[nc], 8);
            sq += __shfl_xor_sync(0xffffffffu, sq, 16);
#pragma unroll
            for (int nc = 0; nc < 4; nc++)
                dp[nc] += __shfl_xor_sync(0xffffffffu, dp[nc], 16);
            float scale = sqrtf(sq) / (1.f + sq + 1e-4f);
#pragma unroll
            for (int nc = 0; nc < 4; nc++) sims[nc] += scale * dp[nc];
        } else {
            sq += __shfl_xor_sync(0xffffffffu, sq, 8);
            sq += __shfl_xor_sync(0xffffffffu, sq, 16);
            float scale = sqrtf(sq) / (1.f + sq + 1e-4f);
#pragma unroll
            for (int j = 0; j < 4; j++) parent[j] = scale * pu[j];
        }
    }

    *(float4*)&out_s[warp][np * 16 + lpg * 4] =
        make_float4(parent[0], parent[1], parent[2], parent[3]);
    __syncthreads();

    const int ch = tid >> 1, half = tid & 1;
    float4 val = make_float4(out_s[half * 4 + 0][ch], out_s[half * 4 + 1][ch],
                             out_s[half * 4 + 2][ch], out_s[half * 4 + 3][ch]);
    *(float4*)&out[((size_t)(pixBase >> 16) * 128 + ch) * 65536
                   + (pixBase & 65535) + half * 4] = val;
}

// ---------------------------------------------------------------------------
extern "C" void kernel_launch(void* const* d_in, const int* in_sizes, int n_in,
                              void* d_out, int out_size) {
    const float* x  = (const float*)d_in[0];   // (4,4,16,256,256)
    const float* Wg = (const float*)d_in[1];   // (128,16,5,5)
    float* out = (float*)d_out;                // (4,8,16,256,256)

    cudaFuncSetAttribute(conv_votes_mma,
                         cudaFuncAttributeMaxDynamicSharedMemorySize, SMEM_TOTAL);
    conv_votes_mma<<<256, 256, SMEM_TOTAL>>>(x, Wg);
    routing_kernel<<<(4 * 256 * 256) / 8, 256>>>(out);
}

// round 13
// speedup vs baseline: 1.1135x; 1.1135x over previous
#include <cuda_runtime.h>
#include <cuda_fp16.h>
#include <cstdint>

#define HH 256
#define WW 256
#define ICH 16
#define HWSZ (HH * WW)

// votes scratch, fp16, NHWC: ((n*H+h)*W+w)*128 + oc   (oc = np*16+lp)
__device__ __half g_votes[(size_t)16 * HH * WW * 128];

// ---- conv smem layout ----
// Input strips: 260 w-slots (slot = w+2), 16 ic fp16 = 32B/slot, XOR swizzle:
// 16B unit u stored at u ^ ((slot>>2)&1). 6-row ring.
#define STRIPB 8320                   // 260 * 32
#define WF_OFF (6 * STRIPB)           // 49920
// W fragment cache: [25 tap][16 ntile][32 lane] * 8B = 102400
#define SMEM_TOTAL (WF_OFF + 102400)  // 152320  -> 1 CTA/SM

__device__ __forceinline__ void mma_f16(float* c, const uint32_t* a,
                                        const uint32_t* b) {
    asm volatile(
        "mma.sync.aligned.m16n8k16.row.col.f32.f16.f16.f32 "
        "{%0,%1,%2,%3}, {%4,%5,%6,%7}, {%8,%9}, {%0,%1,%2,%3};"
        : "+f"(c[0]), "+f"(c[1]), "+f"(c[2]), "+f"(c[3])
        : "r"(a[0]), "r"(a[1]), "r"(a[2]), "r"(a[3]), "r"(b[0]), "r"(b[1]));
}
__device__ __forceinline__ void ldm_x4(uint32_t* r, uint32_t addr) {
    asm volatile(
        "ldmatrix.sync.aligned.m8n8.x4.shared.b16 {%0,%1,%2,%3}, [%4];"
        : "=r"(r[0]), "=r"(r[1]), "=r"(r[2]), "=r"(r[3]) : "r"(addr));
}
__device__ __forceinline__ uint32_t smem_u32(const void* p) {
    uint32_t a;
    asm("{ .reg .u64 t; cvta.to.shared.u64 t, %1; cvt.u32.u64 %0, t; }"
        : "=r"(a) : "l"(p));
    return a;
}

// ---------------------------------------------------------------------------
// Conv: grid = 148 CTAs (ONE wave), 256 thr, 1 CTA/SM. Each CTA owns a
// contiguous row-span of one image: images 0-3 -> 10 spans, images 4-15 ->
// 9 spans (40 + 108 = 148; span <= 29 rows). Per row: M=256 px, N=128 oc,
// warp tile mg=warp&3 (4 m-tiles) x ng=warp>>2 (8 n-tiles), acc=128 regs.
// Single-pass fp16; numerics bit-identical to R12.
// ---------------------------------------------------------------------------
__global__ __launch_bounds__(256, 1)
void conv_votes_mma(const float* __restrict__ x, const float* __restrict__ Wg) {
    extern __shared__ char smem[];
    const uint32_t sb = smem_u32(smem);
    const int tid  = threadIdx.x;
    const int warp = tid >> 5, lane = tid & 31;
    const int gid  = lane >> 2, tig = lane & 3;
    const int mg   = warp & 3, ng = warp >> 2;

    // ---- span mapping: bid -> (n, h0, h1) ----
    const int bid = blockIdx.x;
    int n, s, nspans;
    if (bid < 40) { n = bid / 10; s = bid - n * 10; nspans = 10; }
    else { int r = bid - 40; n = 4 + r / 9; s = r - (n - 4) * 9; nspans = 9; }
    const int h0 = (s * 256) / nspans;
    const int h1 = ((s + 1) * 256) / nspans;

    const float* xn = x + (size_t)n * ICH * HWSZ;

    // ---- W fragment cache: entry e = (tap*16+nt)*32 + lane, 8B ----
    for (int e = tid; e < 25 * 16 * 32; e += 256) {
        int l = e & 31, nt = (e >> 5) & 15, tap = e >> 9;
        int g = l >> 2, t = l & 3;
        const float* wr = Wg + (size_t)(nt * 8 + g) * 400 + tap;
        __half2* dst = (__half2*)(smem + WF_OFF + (size_t)e * 8);
        dst[0] = __halves2half2(__float2half(wr[(2 * t) * 25]),
                                __float2half(wr[(2 * t + 1) * 25]));
        dst[1] = __halves2half2(__float2half(wr[(2 * t + 8) * 25]),
                                __float2half(wr[(2 * t + 9) * 25]));
    }

    // ---- staging: 544 units; unit j: ic2 = j&7, qi = j>>3 (0..67) ----
    auto ldg_unit = [&](const float* xr, bool hok, int ic2, int qi, float4& r0,
                        float4& r1) {
        int q = qi - 1;
        r0 = make_float4(0.f, 0.f, 0.f, 0.f);
        r1 = r0;
        if (hok && (unsigned)q < 64u) {
            r0 = *(const float4*)(xr + (size_t)(2 * ic2) * HWSZ + q * 4);
            r1 = *(const float4*)(xr + (size_t)(2 * ic2 + 1) * HWSZ + q * 4);
        }
    };
    auto sts_unit = [&](const float4& r0, const float4& r1, int ic2, int qi,
                        char* bh) {
        const float a0[4] = {r0.x, r0.y, r0.z, r0.w};
        const float a1[4] = {r1.x, r1.y, r1.z, r1.w};
        const int ubit = ic2 >> 2, ylo = (ic2 & 3) << 2;
        const int sbase = ((qi - 1) << 2) + 2;
#pragma unroll
        for (int d = 0; d < 4; d++) {
            int dd = (d + qi) & 3;
            int slot = sbase + dd;
            if ((unsigned)slot < 260u) {
                int off = slot * 32 + (((ubit ^ (slot >> 2)) & 1) << 4) + ylo;
                *(__half2*)(bh + off) =
                    __float22half2_rn(make_float2(a0[dd], a1[dd]));
            }
        }
    };
    auto stage_row = [&](int h_in) {
        const bool hok = (unsigned)h_in < 256u;
        const float* xr = xn + (size_t)(hok ? h_in : 0) * WW;
        char* bh = smem + ((h_in + 600) % 6) * STRIPB;
        float4 r0, r1;
        ldg_unit(xr, hok, tid & 7, tid >> 3, r0, r1);
        sts_unit(r0, r1, tid & 7, tid >> 3, bh);
        int j = tid + 256;
        ldg_unit(xr, hok, j & 7, j >> 3, r0, r1);
        sts_unit(r0, r1, j & 7, j >> 3, bh);
        if (tid < 32) {
            j = tid + 512;
            ldg_unit(xr, hok, j & 7, j >> 3, r0, r1);
            sts_unit(r0, r1, j & 7, j >> 3, bh);
        }
    };

    // Prologue rows h0-2 .. h0+2
    stage_row(h0 - 2);
    stage_row(h0 - 1);
    stage_row(h0);
    stage_row(h0 + 1);
    stage_row(h0 + 2);
    __syncthreads();

    float acc[4][8][4];
#pragma unroll
    for (int m = 0; m < 4; m++)
#pragma unroll
        for (int nt = 0; nt < 8; nt++)
#pragma unroll
            for (int r = 0; r < 4; r++) acc[m][nt][r] = 0.f;

    // ldmatrix lane geometry: warp's px base = mg*64
    const int r8  = lane & 7;
    const int sA0 = (mg << 6) + r8 + (((lane >> 3) & 1) << 3);
    const int uK  = lane >> 4;

    for (int h = h0; h < h1; h++) {
        const int hs = h + 3;
        const bool hok = hs < 256;

        // Phase 1: prefetch next row (all 3 units) into registers
        float4 p0[2], p1[2], p2a, p2b;
        {
            const float* xr = xn + (size_t)(hok ? hs : 0) * WW;
            ldg_unit(xr, hok, tid & 7, tid >> 3, p0[0], p1[0]);
            int j = tid + 256;
            ldg_unit(xr, hok, j & 7, j >> 3, p0[1], p1[1]);
            if (tid < 32) {
                j = tid + 512;
                ldg_unit(xr, hok, j & 7, j >> 3, p2a, p2b);
            }
        }

        // Phase 2: 25 taps x (4 m x 8 nt) single-pass MMAs
#pragma unroll 1
        for (int ky = 0; ky < 5; ky++) {
            const uint32_t rb32 = sb + ((h - 2 + ky + 600) % 6) * STRIPB;
#pragma unroll
            for (int kx = 0; kx < 5; kx++) {
                const int tap = ky * 5 + kx;
                uint32_t ah[4][4];
#pragma unroll
                for (int m = 0; m < 4; m++) {
                    int s2 = sA0 + (m << 4) + kx;
                    ldm_x4(ah[m], rb32 + s2 * 32
                                  + (((uK ^ (s2 >> 2)) & 1) << 4));
                }
                uint32_t bf[8][2];
#pragma unroll
                for (int nt = 0; nt < 8; nt++) {
                    uint2 vb = *(const uint2*)(smem + WF_OFF
                        + ((tap * 16 + (ng << 3) + nt) << 8) + lane * 8);
                    bf[nt][0] = vb.x;
                    bf[nt][1] = vb.y;
                }
#pragma unroll
                for (int m = 0; m < 4; m++)
#pragma unroll
                    for (int nt = 0; nt < 8; nt++)
                        mma_f16(acc[m][nt], ah[m], bf[nt]);
            }
        }

        // Phase 3: store prefetched row into ring slot (h+3)%6 (STS only)
        {
            char* bh = smem + (hs % 6) * STRIPB;
            sts_unit(p0[0], p1[0], tid & 7, tid >> 3, bh);
            int j = tid + 256;
            sts_unit(p0[1], p1[1], j & 7, j >> 3, bh);
            if (tid < 32) {
                j = tid + 512;
                sts_unit(p2a, p2b, j & 7, j >> 3, bh);
            }
        }

        // Phase 4: epilogue — D row to g_votes (fp16, NHWC, full 128 oc)
        {
            __half* vrow = &g_votes[(((size_t)n * HH + h) * WW) * 128];
#pragma unroll
            for (int m = 0; m < 4; m++) {
                int px = (mg << 6) + (m << 4) + gid;
#pragma unroll
                for (int nt = 0; nt < 8; nt++) {
                    int oc = (ng << 6) + (nt << 3) + (tig << 1);
                    *(__half2*)&vrow[(size_t)px * 128 + oc] =
                        __float22half2_rn(make_float2(acc[m][nt][0],
                                                      acc[m][nt][1]));
                    *(__half2*)&vrow[(size_t)(px + 8) * 128 + oc] =
                        __float22half2_rn(make_float2(acc[m][nt][2],
                                                      acc[m][nt][3]));
                    acc[m][nt][0] = 0.f; acc[m][nt][1] = 0.f;
                    acc[m][nt][2] = 0.f; acc[m][nt][3] = 0.f;
                }
            }
        }
        __syncthreads();
    }
}

// ---------------------------------------------------------------------------
// Routing: unchanged (bit-identical numerics).
// ---------------------------------------------------------------------------
__global__ __launch_bounds__(256)
void routing_kernel(float* __restrict__ out) {
    __shared__ float out_s[8][132];

    const int tid = threadIdx.x;
    const int warp = tid >> 5, lane = tid & 31;
    const int np = lane & 7, lpg = lane >> 3;
    const int pixBase = blockIdx.x << 3;
    const int pix = pixBase + warp;
    const int b = pix >> 16;
    const int hw = pix & 65535;

    float v[4][4];
#pragma unroll
    for (int nc = 0; nc < 4; nc++) {
        const __half2* vp = (const __half2*)
            &g_votes[(((size_t)(b * 4 + nc) << 16) + hw) * 128 + np * 16 + lpg * 4];
        float2 a = __half22float2(vp[0]);
        float2 c2 = __half22float2(vp[1]);
        v[nc][0] = a.x; v[nc][1] = a.y; v[nc][2] = c2.x; v[nc][3] = c2.y;
    }

    float sims[4] = {0.f, 0.f, 0.f, 0.f};
    float parent[4];

#pragma unroll
    for (int it = 0; it < 3; it++) {
        float c[4];
        if (it == 0) {
            c[0] = c[1] = c[2] = c[3] = 0.125f;
        } else {
#pragma unroll
            for (int nc = 0; nc < 4; nc++) {
                float e = __expf(sims[nc]);
                float s = e;
                s += __shfl_xor_sync(0xffffffffu, s, 1);
                s += __shfl_xor_sync(0xffffffffu, s, 2);
                s += __shfl_xor_sync(0xffffffffu, s, 4);
                c[nc] = e / s;
            }
        }
        float pu[4];
#pragma unroll
        for (int j = 0; j < 4; j++)
            pu[j] = c[0] * v[0][j] + c[1] * v[1][j] + c[2] * v[2][j]
                  + c[3] * v[3][j];
        float sq = pu[0] * pu[0] + pu[1] * pu[1] + pu[2] * pu[2] + pu[3] * pu[3];

        if (it < 2) {
            float dp[4];
#pragma unroll
            for (int nc = 0; nc < 4; nc++)
                dp[nc] = v[nc][0] * pu[0] + v[nc][1] * pu[1]
                       + v[nc][2] * pu[2] + v[nc][3] * pu[3];
            sq += __shfl_xor_sync(0xffffffffu, sq, 8);
#pragma unroll
            for (int nc = 0; nc < 4; nc++)
                dp[nc] += __shfl_xor_sync(0xffffffffu, dp[nc], 8);
            sq += __shfl_xor_sync(0xffffffffu, sq, 16);
#pragma unroll
            for (int nc = 0; nc < 4; nc++)
                dp[nc] += __shfl_xor_sync(0xffffffffu, dp[nc], 16);
            float scale = sqrtf(sq) / (1.f + sq + 1e-4f);
#pragma unroll
            for (int nc = 0; nc < 4; nc++) sims[nc] += scale * dp[nc];
        } else {
            sq += __shfl_xor_sync(0xffffffffu, sq, 8);
            sq += __shfl_xor_sync(0xffffffffu, sq, 16);
            float scale = sqrtf(sq) / (1.f + sq + 1e-4f);
#pragma unroll
            for (int j = 0; j < 4; j++) parent[j] = scale * pu[j];
        }
    }

    *(float4*)&out_s[warp][np * 16 + lpg * 4] =
        make_float4(parent[0], parent[1], parent[2], parent[3]);
    __syncthreads();

    const int ch = tid >> 1, half = tid & 1;
    float4 val = make_float4(out_s[half * 4 + 0][ch], out_s[half * 4 + 1][ch],
                             out_s[half * 4 + 2][ch], out_s[half * 4 + 3][ch]);
    *(float4*)&out[((size_t)(pixBase >> 16) * 128 + ch) * 65536
                   + (pixBase & 65535) + half * 4] = val;
}

// ---------------------------------------------------------------------------
extern "C" void kernel_launch(void* const* d_in, const int* in_sizes, int n_in,
                              void* d_out, int out_size) {
    const float* x  = (const float*)d_in[0];   // (4,4,16,256,256)
    const float* Wg = (const float*)d_in[1];   // (128,16,5,5)
    float* out = (float*)d_out;                // (4,8,16,256,256)

    cudaFuncSetAttribute(conv_votes_mma,
                         cudaFuncAttributeMaxDynamicSharedMemorySize, SMEM_TOTAL);
    conv_votes_mma<<<148, 256, SMEM_TOTAL>>>(x, Wg);
    routing_kernel<<<(4 * 256 * 256) / 8, 256>>>(out);
}

// round 14
// speedup vs baseline: 1.1182x; 1.0042x over previous
#include <cuda_runtime.h>
#include <cuda_fp16.h>
#include <cstdint>

#define HH 256
#define WW 256
#define ICH 16
#define HWSZ (HH * WW)

// votes scratch, fp16, NHWC: ((n*H+h)*W+w)*128 + oc   (oc = np*16+lp)
__device__ __half g_votes[(size_t)16 * HH * WW * 128];

// ---- conv smem layout ----
// Input strips: 260 w-slots (slot = w+2), 16 ic fp16 = 32B/slot, XOR swizzle:
// 16B unit u stored at u ^ ((slot>>2)&1). 6-row ring.
#define STRIPB 8320                   // 260 * 32
#define WF_OFF (6 * STRIPB)           // 49920
// W fragment cache: [25 tap][16 ntile][32 lane] * 8B = 102400
#define SMEM_TOTAL (WF_OFF + 102400)  // 152320  -> 1 CTA/SM

__device__ __forceinline__ void mma_f16(float* c, const uint32_t* a,
                                        const uint32_t* b) {
    asm volatile(
        "mma.sync.aligned.m16n8k16.row.col.f32.f16.f16.f32 "
        "{%0,%1,%2,%3}, {%4,%5,%6,%7}, {%8,%9}, {%0,%1,%2,%3};"
        : "+f"(c[0]), "+f"(c[1]), "+f"(c[2]), "+f"(c[3])
        : "r"(a[0]), "r"(a[1]), "r"(a[2]), "r"(a[3]), "r"(b[0]), "r"(b[1]));
}
__device__ __forceinline__ void ldm_x4(uint32_t* r, uint32_t addr) {
    asm volatile(
        "ldmatrix.sync.aligned.m8n8.x4.shared.b16 {%0,%1,%2,%3}, [%4];"
        : "=r"(r[0]), "=r"(r[1]), "=r"(r[2]), "=r"(r[3]) : "r"(addr));
}
__device__ __forceinline__ uint32_t smem_u32(const void* p) {
    uint32_t a;
    asm("{ .reg .u64 t; cvta.to.shared.u64 t, %1; cvt.u32.u64 %0, t; }"
        : "=r"(a) : "l"(p));
    return a;
}

// ---------------------------------------------------------------------------
// Conv: grid = 148 CTAs (ONE wave), 512 thr, 1 CTA/SM (4 warps/SMSP for
// latency hiding). Span mapping: images 0-3 -> 10 spans, 4-15 -> 9 spans.
// Per row: M=256 px, N=128 oc. Warp tile: mg = warp&7 (2 m-tiles = 32 px),
// ng = warp>>3 (8 n-tiles = 64 oc); acc = 64 regs. Single-pass fp16;
// numerics bit-identical to R13 (same tap order, same conversions).
// ---------------------------------------------------------------------------
__global__ __launch_bounds__(512, 1)
void conv_votes_mma(const float* __restrict__ x, const float* __restrict__ Wg) {
    extern __shared__ char smem[];
    const uint32_t sb = smem_u32(smem);
    const int tid  = threadIdx.x;
    const int warp = tid >> 5, lane = tid & 31;
    const int gid  = lane >> 2, tig = lane & 3;
    const int mg   = warp & 7, ng = warp >> 3;

    // ---- span mapping: bid -> (n, h0, h1) ----
    const int bid = blockIdx.x;
    int n, s, nspans;
    if (bid < 40) { n = bid / 10; s = bid - n * 10; nspans = 10; }
    else { int r = bid - 40; n = 4 + r / 9; s = r - (n - 4) * 9; nspans = 9; }
    const int h0 = (s * 256) / nspans;
    const int h1 = ((s + 1) * 256) / nspans;

    const float* xn = x + (size_t)n * ICH * HWSZ;

    // ---- W fragment cache: entry e = (tap*16+nt)*32 + lane, 8B ----
    for (int e = tid; e < 25 * 16 * 32; e += 512) {
        int l = e & 31, nt = (e >> 5) & 15, tap = e >> 9;
        int g = l >> 2, t = l & 3;
        const float* wr = Wg + (size_t)(nt * 8 + g) * 400 + tap;
        __half2* dst = (__half2*)(smem + WF_OFF + (size_t)e * 8);
        dst[0] = __halves2half2(__float2half(wr[(2 * t) * 25]),
                                __float2half(wr[(2 * t + 1) * 25]));
        dst[1] = __halves2half2(__float2half(wr[(2 * t + 8) * 25]),
                                __float2half(wr[(2 * t + 9) * 25]));
    }

    // ---- staging: 544 units; unit j: ic2 = j&7, qi = j>>3 (0..67) ----
    auto ldg_unit = [&](const float* xr, bool hok, int ic2, int qi, float4& r0,
                        float4& r1) {
        int q = qi - 1;
        r0 = make_float4(0.f, 0.f, 0.f, 0.f);
        r1 = r0;
        if (hok && (unsigned)q < 64u) {
            r0 = *(const float4*)(xr + (size_t)(2 * ic2) * HWSZ + q * 4);
            r1 = *(const float4*)(xr + (size_t)(2 * ic2 + 1) * HWSZ + q * 4);
        }
    };
    auto sts_unit = [&](const float4& r0, const float4& r1, int ic2, int qi,
                        char* bh) {
        const float a0[4] = {r0.x, r0.y, r0.z, r0.w};
        const float a1[4] = {r1.x, r1.y, r1.z, r1.w};
        const int ubit = ic2 >> 2, ylo = (ic2 & 3) << 2;
        const int sbase = ((qi - 1) << 2) + 2;
#pragma unroll
        for (int d = 0; d < 4; d++) {
            int dd = (d + qi) & 3;
            int slot = sbase + dd;
            if ((unsigned)slot < 260u) {
                int off = slot * 32 + (((ubit ^ (slot >> 2)) & 1) << 4) + ylo;
                *(__half2*)(bh + off) =
                    __float22half2_rn(make_float2(a0[dd], a1[dd]));
            }
        }
    };
    auto stage_row = [&](int h_in) {
        const bool hok = (unsigned)h_in < 256u;
        const float* xr = xn + (size_t)(hok ? h_in : 0) * WW;
        char* bh = smem + ((h_in + 600) % 6) * STRIPB;
        float4 r0, r1;
        ldg_unit(xr, hok, tid & 7, tid >> 3, r0, r1);
        sts_unit(r0, r1, tid & 7, tid >> 3, bh);
        if (tid < 32) {
            int j = tid + 512;
            ldg_unit(xr, hok, j & 7, j >> 3, r0, r1);
            sts_unit(r0, r1, j & 7, j >> 3, bh);
        }
    };

    // Prologue rows h0-2 .. h0+2
    stage_row(h0 - 2);
    stage_row(h0 - 1);
    stage_row(h0);
    stage_row(h0 + 1);
    stage_row(h0 + 2);
    __syncthreads();

    float acc[2][8][4];
#pragma unroll
    for (int m = 0; m < 2; m++)
#pragma unroll
        for (int nt = 0; nt < 8; nt++)
#pragma unroll
            for (int r = 0; r < 4; r++) acc[m][nt][r] = 0.f;

    // ldmatrix lane geometry: warp's px base = mg*32
    const int r8  = lane & 7;
    const int sA0 = (mg << 5) + r8 + (((lane >> 3) & 1) << 3);
    const int uK  = lane >> 4;

    for (int h = h0; h < h1; h++) {
        const int hs = h + 3;
        const bool hok = hs < 256;

        // Phase 1: prefetch next row (all units) into registers
        float4 p0, p1, p2a, p2b;
        {
            const float* xr = xn + (size_t)(hok ? hs : 0) * WW;
            ldg_unit(xr, hok, tid & 7, tid >> 3, p0, p1);
            if (tid < 32) {
                int j = tid + 512;
                ldg_unit(xr, hok, j & 7, j >> 3, p2a, p2b);
            }
        }

        // Phase 2: 25 taps x (2 m x 8 nt) single-pass MMAs
#pragma unroll 1
        for (int ky = 0; ky < 5; ky++) {
            const uint32_t rb32 = sb + ((h - 2 + ky + 600) % 6) * STRIPB;
#pragma unroll
            for (int kx = 0; kx < 5; kx++) {
                const int tap = ky * 5 + kx;
                uint32_t ah[2][4];
#pragma unroll
                for (int m = 0; m < 2; m++) {
                    int s2 = sA0 + (m << 4) + kx;
                    ldm_x4(ah[m], rb32 + s2 * 32
                                  + (((uK ^ (s2 >> 2)) & 1) << 4));
                }
                uint32_t bf[8][2];
#pragma unroll
                for (int nt = 0; nt < 8; nt++) {
                    uint2 vb = *(const uint2*)(smem + WF_OFF
                        + ((tap * 16 + (ng << 3) + nt) << 8) + lane * 8);
                    bf[nt][0] = vb.x;
                    bf[nt][1] = vb.y;
                }
#pragma unroll
                for (int m = 0; m < 2; m++)
#pragma unroll
                    for (int nt = 0; nt < 8; nt++)
                        mma_f16(acc[m][nt], ah[m], bf[nt]);
            }
        }

        // Phase 3: store prefetched row into ring slot (h+3)%6 (STS only)
        {
            char* bh = smem + (hs % 6) * STRIPB;
            sts_unit(p0, p1, tid & 7, tid >> 3, bh);
            if (tid < 32) {
                int j = tid + 512;
                sts_unit(p2a, p2b, j & 7, j >> 3, bh);
            }
        }

        // Phase 4: epilogue — D row to g_votes (fp16, NHWC, full 128 oc)
        {
            __half* vrow = &g_votes[(((size_t)n * HH + h) * WW) * 128];
#pragma unroll
            for (int m = 0; m < 2; m++) {
                int px = (mg << 5) + (m << 4) + gid;
#pragma unroll
                for (int nt = 0; nt < 8; nt++) {
                    int oc = (ng << 6) + (nt << 3) + (tig << 1);
                    *(__half2*)&vrow[(size_t)px * 128 + oc] =
                        __float22half2_rn(make_float2(acc[m][nt][0],
                                                      acc[m][nt][1]));
                    *(__half2*)&vrow[(size_t)(px + 8) * 128 + oc] =
                        __float22half2_rn(make_float2(acc[m][nt][2],
                                                      acc[m][nt][3]));
                    acc[m][nt][0] = 0.f; acc[m][nt][1] = 0.f;
                    acc[m][nt][2] = 0.f; acc[m][nt][3] = 0.f;
                }
            }
        }
        __syncthreads();
    }
}

// ---------------------------------------------------------------------------
// Routing: unchanged (bit-identical numerics).
// ---------------------------------------------------------------------------
__global__ __launch_bounds__(256)
void routing_kernel(float* __restrict__ out) {
    __shared__ float out_s[8][132];

    const int tid = threadIdx.x;
    const int warp = tid >> 5, lane = tid & 31;
    const int np = lane & 7, lpg = lane >> 3;
    const int pixBase = blockIdx.x << 3;
    const int pix = pixBase + warp;
    const int b = pix >> 16;
    const int hw = pix & 65535;

    float v[4][4];
#pragma unroll
    for (int nc = 0; nc < 4; nc++) {
        const __half2* vp = (const __half2*)
            &g_votes[(((size_t)(b * 4 + nc) << 16) + hw) * 128 + np * 16 + lpg * 4];
        float2 a = __half22float2(vp[0]);
        float2 c2 = __half22float2(vp[1]);
        v[nc][0] = a.x; v[nc][1] = a.y; v[nc][2] = c2.x; v[nc][3] = c2.y;
    }

    float sims[4] = {0.f, 0.f, 0.f, 0.f};
    float parent[4];

#pragma unroll
    for (int it = 0; it < 3; it++) {
        float c[4];
        if (it == 0) {
            c[0] = c[1] = c[2] = c[3] = 0.125f;
        } else {
#pragma unroll
            for (int nc = 0; nc < 4; nc++) {
                float e = __expf(sims[nc]);
                float s = e;
                s += __shfl_xor_sync(0xffffffffu, s, 1);
                s += __shfl_xor_sync(0xffffffffu, s, 2);
                s += __shfl_xor_sync(0xffffffffu, s, 4);
                c[nc] = e / s;
            }
        }
        float pu[4];
#pragma unroll
        for (int j = 0; j < 4; j++)
            pu[j] = c[0] * v[0][j] + c[1] * v[1][j] + c[2] * v[2][j]
                  + c[3] * v[3][j];
        float sq = pu[0] * pu[0] + pu[1] * pu[1] + pu[2] * pu[2] + pu[3] * pu[3];

        if (it < 2) {
            float dp[4];
#pragma unroll
            for (int nc = 0; nc < 4; nc++)
                dp[nc] = v[nc][0] * pu[0] + v[nc][1] * pu[1]
                       + v[nc][2] * pu[2] + v[nc][3] * pu[3];
            sq += __shfl_xor_sync(0xffffffffu, sq, 8);
#pragma unroll
            for (int nc = 0; nc < 4; nc++)
                dp[nc] += __shfl_xor_sync(0xffffffffu, dp[nc], 8);
            sq += __shfl_xor_sync(0xffffffffu, sq, 16);
#pragma unroll
            for (int nc = 0; nc < 4; nc++)
                dp[nc] += __shfl_xor_sync(0xffffffffu, dp[nc], 16);
            float scale = sqrtf(sq) / (1.f + sq + 1e-4f);
#pragma unroll
            for (int nc = 0; nc < 4; nc++) sims[nc] += scale * dp[nc];
        } else {
            sq += __shfl_xor_sync(0xffffffffu, sq, 8);
            sq += __shfl_xor_sync(0xffffffffu, sq, 16);
            float scale = sqrtf(sq) / (1.f + sq + 1e-4f);
#pragma unroll
            for (int j = 0; j < 4; j++) parent[j] = scale * pu[j];
        }
    }

    *(float4*)&out_s[warp][np * 16 + lpg * 4] =
        make_float4(parent[0], parent[1], parent[2], parent[3]);
    __syncthreads();

    const int ch = tid >> 1, half = tid & 1;
    float4 val = make_float4(out_s[half * 4 + 0][ch], out_s[half * 4 + 1][ch],
                             out_s[half * 4 + 2][ch], out_s[half * 4 + 3][ch]);
    *(float4*)&out[((size_t)(pixBase >> 16) * 128 + ch) * 65536
                   + (pixBase & 65535) + half * 4] = val;
}

// ---------------------------------------------------------------------------
extern "C" void kernel_launch(void* const* d_in, const int* in_sizes, int n_in,
                              void* d_out, int out_size) {
    const float* x  = (const float*)d_in[0];   // (4,4,16,256,256)
    const float* Wg = (const float*)d_in[1];   // (128,16,5,5)
    float* out = (float*)d_out;                // (4,8,16,256,256)

    cudaFuncSetAttribute(conv_votes_mma,
                         cudaFuncAttributeMaxDynamicSharedMemorySize, SMEM_TOTAL);
    conv_votes_mma<<<148, 512, SMEM_TOTAL>>>(x, Wg);
    routing_kernel<<<(4 * 256 * 256) / 8, 256>>>(out);
}